// round 2
// baseline (speedup 1.0000x reference)
#include <cuda_runtime.h>
#include <cuda_bf16.h>
#include <cstdint>

// Problem constants (fixed by the reference)
#define NN 50000     // nodes
#define EE 600000    // edges
#define GG 256       // graphs
#define HH 128       // hidden = feature dim

// ---------------- scratch (static __device__, no allocation) ----------------
__device__ float g_tmp[NN * HH];        // h = x @ W  (GEMM output)
__device__ float g_buf[NN * HH];        // layer output (ping)
__device__ float g_dis[NN];             // deg_inv_sqrt
__device__ int   g_deg[NN];             // in-degree histogram
__device__ int   g_row_off[NN + 1];     // CSR offsets by dst
__device__ int   g_fill[NN];            // fill cursors
__device__ int   g_src_sorted[EE];      // src node per CSR slot
__device__ float g_norm_sorted[EE];     // dis[src]*dis[dst] per CSR slot
__device__ float g_cnt[GG];             // nodes per graph
__device__ int   g_idx64;               // 1 if edge_index/batch_idx are int64

// index fetch honoring detected width
__device__ __forceinline__ int idx_at(const void* p, long long i) {
    if (g_idx64) return (int)((const long long*)p)[i];
    return ((const int*)p)[i];
}

// ---------------- dtype detection: int64 has zero high words ----------------
__global__ void detect_kernel(const int* __restrict__ ei_raw) {
    // If buffer is int64 (little-endian, values < 2^31), every odd 32-bit
    // word of the first 32 elements is 0. For int32 data these words are
    // random node ids in [0, 50000) — all-zero has probability ~0.
    int all_zero = 1;
    for (int i = 1; i < 64; i += 2)
        if (ei_raw[i] != 0) all_zero = 0;
    g_idx64 = all_zero;
}

// ---------------- init: zero everything that accumulates ----------------
__global__ void init_kernel(float* __restrict__ out) {
    int i = blockIdx.x * blockDim.x + threadIdx.x;
    if (i < NN) { g_deg[i] = 0; g_fill[i] = 0; }
    if (i < GG * HH) out[i] = 0.0f;
    if (i < GG) g_cnt[i] = 0.0f;
}

// ---------------- degree histogram over dst ----------------
__global__ void deg_kernel(const void* __restrict__ edge_index) {
    int e = blockIdx.x * blockDim.x + threadIdx.x;
    if (e >= EE) return;
    int d = idx_at(edge_index, (long long)EE + e);
    atomicAdd(&g_deg[d], 1);
}

// ---------------- deg_inv_sqrt ----------------
__global__ void dis_kernel() {
    int i = blockIdx.x * blockDim.x + threadIdx.x;
    if (i >= NN) return;
    g_dis[i] = rsqrtf((float)g_deg[i] + 1.0f);
}

// ---------------- single-block exclusive scan of g_deg -> g_row_off ----------------
__global__ void scan_kernel() {
    __shared__ int sh[1024];
    __shared__ int s_carry;
    int t = threadIdx.x;
    if (t == 0) { s_carry = 0; g_row_off[0] = 0; }
    __syncthreads();
    for (int base = 0; base < NN; base += 1024) {
        int i = base + t;
        int v = (i < NN) ? g_deg[i] : 0;
        sh[t] = v;
        __syncthreads();
        #pragma unroll
        for (int off = 1; off < 1024; off <<= 1) {
            int tmp = (t >= off) ? sh[t - off] : 0;
            __syncthreads();
            sh[t] += tmp;
            __syncthreads();
        }
        if (i < NN) g_row_off[i + 1] = s_carry + sh[t];
        int total = sh[1023];
        __syncthreads();
        if (t == 0) s_carry += total;
        __syncthreads();
    }
}

// ---------------- CSR fill: scatter edges into dst-sorted order ----------------
__global__ void fill_kernel(const void* __restrict__ edge_index) {
    int e = blockIdx.x * blockDim.x + threadIdx.x;
    if (e >= EE) return;
    int s = idx_at(edge_index, e);
    int d = idx_at(edge_index, (long long)EE + e);
    int p = g_row_off[d] + atomicAdd(&g_fill[d], 1);
    g_src_sorted[p]  = s;
    g_norm_sorted[p] = g_dis[s] * g_dis[d];
}

// ---------------- SGEMM: C[M,128] = A[M,128] @ W[128,128] ----------------
// 128x128 block tile, 256 threads, 8x8 micro-tile per thread, K chunks of 16.
__global__ __launch_bounds__(256, 2) void gemm_kernel(
    const float* __restrict__ A, const float* __restrict__ W,
    float* __restrict__ C, int M)
{
    __shared__ float As[16][132];   // transposed: [k][m], padded
    __shared__ float Ws[16][128];   // [k][n]

    int tid = threadIdx.x;
    int m0  = blockIdx.x * 128;
    int r0  = (tid >> 4) << 3;      // row offset within tile (0..120)
    int c0  = (tid & 15) << 3;      // col offset within tile (0..120)

    float acc[8][8];
    #pragma unroll
    for (int i = 0; i < 8; i++)
        #pragma unroll
        for (int j = 0; j < 8; j++) acc[i][j] = 0.0f;

    for (int k0 = 0; k0 < 128; k0 += 16) {
        // A tile: 128 rows x 16 k, store transposed
        #pragma unroll
        for (int it = 0; it < 2; it++) {
            int idx = tid + it * 256;           // 0..511 float4 slots
            int row = idx >> 2;
            int c4  = (idx & 3) << 2;
            float4 v = make_float4(0.f, 0.f, 0.f, 0.f);
            int m = m0 + row;
            if (m < M)
                v = *reinterpret_cast<const float4*>(&A[(size_t)m * 128 + k0 + c4]);
            As[c4 + 0][row] = v.x;
            As[c4 + 1][row] = v.y;
            As[c4 + 2][row] = v.z;
            As[c4 + 3][row] = v.w;
        }
        // W tile: 16 k x 128 n
        #pragma unroll
        for (int it = 0; it < 2; it++) {
            int idx = tid + it * 256;
            int row = idx >> 5;
            int c   = (idx & 31) << 2;
            *reinterpret_cast<float4*>(&Ws[row][c]) =
                *reinterpret_cast<const float4*>(&W[(k0 + row) * 128 + c]);
        }
        __syncthreads();

        #pragma unroll
        for (int kk = 0; kk < 16; kk++) {
            float4 a0 = *reinterpret_cast<float4*>(&As[kk][r0]);
            float4 a1 = *reinterpret_cast<float4*>(&As[kk][r0 + 4]);
            float4 w0 = *reinterpret_cast<float4*>(&Ws[kk][c0]);
            float4 w1 = *reinterpret_cast<float4*>(&Ws[kk][c0 + 4]);
            float a[8] = {a0.x, a0.y, a0.z, a0.w, a1.x, a1.y, a1.z, a1.w};
            float w[8] = {w0.x, w0.y, w0.z, w0.w, w1.x, w1.y, w1.z, w1.w};
            #pragma unroll
            for (int i = 0; i < 8; i++)
                #pragma unroll
                for (int j = 0; j < 8; j++)
                    acc[i][j] += a[i] * w[j];
        }
        __syncthreads();
    }

    #pragma unroll
    for (int i = 0; i < 8; i++) {
        int m = m0 + r0 + i;
        if (m < M) {
            float4 o0 = make_float4(acc[i][0], acc[i][1], acc[i][2], acc[i][3]);
            float4 o1 = make_float4(acc[i][4], acc[i][5], acc[i][6], acc[i][7]);
            *reinterpret_cast<float4*>(&C[(size_t)m * 128 + c0])     = o0;
            *reinterpret_cast<float4*>(&C[(size_t)m * 128 + c0 + 4]) = o1;
        }
    }
}

// ---------------- aggregation (gather over CSR) + bias + relu ----------------
// One warp per node; lane handles 4 consecutive channels via float4.
// do_pool: instead of writing out, relu-row is atomically pooled into d_out.
__global__ void agg_kernel(const float* __restrict__ h,
                           const float* __restrict__ bias,
                           float* __restrict__ out,
                           int do_pool,
                           const void* __restrict__ batch_idx,
                           float* __restrict__ pool)
{
    int warp = (blockIdx.x * blockDim.x + threadIdx.x) >> 5;
    int lane = threadIdx.x & 31;
    if (warp >= NN) return;
    int n = warp;

    float dn   = g_dis[n];
    float self = dn * dn;

    float4 acc = *reinterpret_cast<const float4*>(&h[(size_t)n * 128 + lane * 4]);
    acc.x *= self; acc.y *= self; acc.z *= self; acc.w *= self;

    int s0 = g_row_off[n];
    int s1 = g_row_off[n + 1];
    for (int e = s0; e < s1; e++) {
        int   s   = g_src_sorted[e];
        float nrm = g_norm_sorted[e];
        float4 v  = *reinterpret_cast<const float4*>(&h[(size_t)s * 128 + lane * 4]);
        acc.x += v.x * nrm;
        acc.y += v.y * nrm;
        acc.z += v.z * nrm;
        acc.w += v.w * nrm;
    }

    float4 bb = *reinterpret_cast<const float4*>(&bias[lane * 4]);
    acc.x = fmaxf(acc.x + bb.x, 0.0f);
    acc.y = fmaxf(acc.y + bb.y, 0.0f);
    acc.z = fmaxf(acc.z + bb.z, 0.0f);
    acc.w = fmaxf(acc.w + bb.w, 0.0f);

    if (!do_pool) {
        *reinterpret_cast<float4*>(&out[(size_t)n * 128 + lane * 4]) = acc;
    } else {
        int g = idx_at(batch_idx, n);
        float* p = &pool[g * 128 + lane * 4];
        atomicAdd(p + 0, acc.x);
        atomicAdd(p + 1, acc.y);
        atomicAdd(p + 2, acc.z);
        atomicAdd(p + 3, acc.w);
        if (lane == 0) atomicAdd(&g_cnt[g], 1.0f);
    }
}

// ---------------- final divide: mean pool ----------------
__global__ void divide_kernel(float* __restrict__ out) {
    int i = blockIdx.x * blockDim.x + threadIdx.x;
    if (i >= GG * HH) return;
    int g = i >> 7;
    out[i] /= fmaxf(g_cnt[g], 1.0f);
}

// ---------------- launch ----------------
extern "C" void kernel_launch(void* const* d_in, const int* in_sizes, int n_in,
                              void* d_out, int out_size)
{
    const float* x    = (const float*)d_in[0];
    const float* W1   = (const float*)d_in[1];
    const float* b1   = (const float*)d_in[2];
    const float* W2   = (const float*)d_in[3];
    const float* b2   = (const float*)d_in[4];
    const float* W3   = (const float*)d_in[5];
    const float* b3   = (const float*)d_in[6];
    const void*  ei   = d_in[7];
    const void*  bidx = d_in[8];
    float* out = (float*)d_out;

    float *tmp, *buf;
    cudaGetSymbolAddress((void**)&tmp, g_tmp);
    cudaGetSymbolAddress((void**)&buf, g_buf);
    (void)in_sizes; (void)n_in; (void)out_size;

    const int T = 256;

    // graph structure build
    detect_kernel<<<1, 1>>>((const int*)ei);
    init_kernel<<<(NN + T - 1) / T, T>>>(out);
    deg_kernel<<<(EE + T - 1) / T, T>>>(ei);
    dis_kernel<<<(NN + T - 1) / T, T>>>();
    scan_kernel<<<1, 1024>>>();
    fill_kernel<<<(EE + T - 1) / T, T>>>(ei);

    int gemm_blocks = (NN + 127) / 128;
    int agg_blocks  = (NN * 32 + T - 1) / T;   // one warp per node

    // layer 1
    gemm_kernel<<<gemm_blocks, 256>>>(x, W1, tmp, NN);
    agg_kernel<<<agg_blocks, T>>>(tmp, b1, buf, 0, bidx, out);
    // layer 2
    gemm_kernel<<<gemm_blocks, 256>>>(buf, W2, tmp, NN);
    agg_kernel<<<agg_blocks, T>>>(tmp, b2, buf, 0, bidx, out);
    // layer 3 (fused pool)
    gemm_kernel<<<gemm_blocks, 256>>>(buf, W3, tmp, NN);
    agg_kernel<<<agg_blocks, T>>>(tmp, b3, buf, 1, bidx, out);

    divide_kernel<<<(GG * HH + T - 1) / T, T>>>(out);
}

// round 3
// speedup vs baseline: 1.6544x; 1.6544x over previous
#include <cuda_runtime.h>
#include <cuda_bf16.h>
#include <cstdint>

#define NN 50000
#define EE 600000
#define GG 256
#define HH 128
#define SCAN_B 512
#define NP ((NN + SCAN_B - 1) / SCAN_B)   // 98 scan partials

// ---------------- scratch ----------------
__device__ float g_tmp[NN * HH];                 // GEMM output (fp32)
__device__ __nv_bfloat16 g_ah[NN * HH];          // GEMM input hi
__device__ __nv_bfloat16 g_al[NN * HH];          // GEMM input lo
__device__ __nv_bfloat16 g_wh[3 * HH * HH];      // weights hi
__device__ __nv_bfloat16 g_wl[3 * HH * HH];      // weights lo
__device__ float g_dis[NN];
__device__ int   g_deg[NN];
__device__ int   g_row_off[NN + 1];
__device__ int   g_fill[NN];
__device__ int   g_src_sorted[EE];
__device__ float g_norm_sorted[EE];
__device__ float g_cnt[GG];
__device__ int   g_part[NP];
__device__ int   g_idx64;

__device__ __forceinline__ int idx_at(const void* p, long long i) {
    if (g_idx64) return (int)((const long long*)p)[i];
    return ((const int*)p)[i];
}

// ---------------- dtype detection ----------------
__global__ void detect_kernel(const int* __restrict__ ei_raw) {
    int all_zero = 1;
    for (int i = 1; i < 64; i += 2)
        if (ei_raw[i] != 0) all_zero = 0;
    g_idx64 = all_zero;
}

// ---------------- init ----------------
__global__ void init_kernel(float* __restrict__ out) {
    int i = blockIdx.x * blockDim.x + threadIdx.x;
    if (i < NN) { g_deg[i] = 0; g_fill[i] = 0; }
    if (i < GG * HH) out[i] = 0.0f;
    if (i < GG) g_cnt[i] = 0.0f;
}

// ---------------- degree histogram ----------------
__global__ void deg_kernel(const void* __restrict__ edge_index) {
    int e = blockIdx.x * blockDim.x + threadIdx.x;
    if (e >= EE) return;
    atomicAdd(&g_deg[idx_at(edge_index, (long long)EE + e)], 1);
}

__global__ void dis_kernel() {
    int i = blockIdx.x * blockDim.x + threadIdx.x;
    if (i >= NN) return;
    g_dis[i] = rsqrtf((float)g_deg[i] + 1.0f);
}

// ---------------- 3-phase scan ----------------
__global__ void scan1_kernel() {
    int b = blockIdx.x, t = threadIdx.x;
    int i = b * SCAN_B + t;
    int lane = t & 31, w = t >> 5;
    int x = (i < NN) ? g_deg[i] : 0;
    #pragma unroll
    for (int off = 1; off < 32; off <<= 1) {
        int y = __shfl_up_sync(0xffffffffu, x, off);
        if (lane >= off) x += y;
    }
    __shared__ int wsum[16];
    if (lane == 31) wsum[w] = x;
    __syncthreads();
    if (w == 0) {
        int s = (lane < 16) ? wsum[lane] : 0;
        #pragma unroll
        for (int off = 1; off < 16; off <<= 1) {
            int y = __shfl_up_sync(0xffffffffu, s, off);
            if (lane >= off) s += y;
        }
        if (lane < 16) wsum[lane] = s;
    }
    __syncthreads();
    int inc = x + ((w > 0) ? wsum[w - 1] : 0);   // block-inclusive
    if (i < NN) g_row_off[i + 1] = inc;
    if (t == SCAN_B - 1) g_part[b] = inc;
}

__global__ void scan2_kernel() {   // 1 block, 128 threads, scans NP partials
    int t = threadIdx.x;
    int lane = t & 31, w = t >> 5;
    int x = (t < NP) ? g_part[t] : 0;
    #pragma unroll
    for (int off = 1; off < 32; off <<= 1) {
        int y = __shfl_up_sync(0xffffffffu, x, off);
        if (lane >= off) x += y;
    }
    __shared__ int wsum[4];
    if (lane == 31) wsum[w] = x;
    __syncthreads();
    if (w == 0 && lane < 4) {
        int s = wsum[lane];
        #pragma unroll
        for (int off = 1; off < 4; off <<= 1) {
            int y = __shfl_up_sync(0x0000000fu, s, off);
            if (lane >= off) s += y;
        }
        wsum[lane] = s;
    }
    __syncthreads();
    int inc = x + ((w > 0) ? wsum[w - 1] : 0);
    if (t < NP) g_part[t] = inc;   // inclusive partials
}

__global__ void scan3_kernel() {
    int b = blockIdx.x, t = threadIdx.x;
    int i = b * SCAN_B + t;
    if (b > 0 && i < NN) g_row_off[i + 1] += g_part[b - 1];
    if (i == 0) g_row_off[0] = 0;
}

// ---------------- CSR fill ----------------
__global__ void fill_kernel(const void* __restrict__ edge_index) {
    int e = blockIdx.x * blockDim.x + threadIdx.x;
    if (e >= EE) return;
    int s = idx_at(edge_index, e);
    int d = idx_at(edge_index, (long long)EE + e);
    int p = g_row_off[d] + atomicAdd(&g_fill[d], 1);
    g_src_sorted[p]  = s;
    g_norm_sorted[p] = g_dis[s] * g_dis[d];
}

// ---------------- fp32 -> bf16 hi/lo splits ----------------
__device__ __forceinline__ void split_bf16(float v, __nv_bfloat16& h, __nv_bfloat16& l) {
    h = __float2bfloat16_rn(v);
    l = __float2bfloat16_rn(v - __bfloat162float(h));
}

__global__ void convertx_kernel(const float* __restrict__ x) {
    int i = blockIdx.x * blockDim.x + threadIdx.x;   // float4 index
    if (i >= NN * HH / 4) return;
    float4 v = ((const float4*)x)[i];
    __nv_bfloat16 h0,h1,h2,h3,l0,l1,l2,l3;
    split_bf16(v.x,h0,l0); split_bf16(v.y,h1,l1);
    split_bf16(v.z,h2,l2); split_bf16(v.w,h3,l3);
    __nv_bfloat162* ph = (__nv_bfloat162*)&g_ah[i*4];
    __nv_bfloat162* pl = (__nv_bfloat162*)&g_al[i*4];
    ph[0] = __nv_bfloat162{h0,h1}; ph[1] = __nv_bfloat162{h2,h3};
    pl[0] = __nv_bfloat162{l0,l1}; pl[1] = __nv_bfloat162{l2,l3};
}

__global__ void convertw_kernel(const float* __restrict__ W1,
                                const float* __restrict__ W2,
                                const float* __restrict__ W3) {
    int i = blockIdx.x * blockDim.x + threadIdx.x;   // 0 .. 3*16384
    if (i >= 3 * HH * HH) return;
    int which = i >> 14;
    int j = i & (HH * HH - 1);
    const float* W = (which == 0) ? W1 : (which == 1) ? W2 : W3;
    __nv_bfloat16 h, l;
    split_bf16(W[j], h, l);
    g_wh[i] = h; g_wl[i] = l;
}

// ---------------- mma helpers ----------------
__device__ __forceinline__ uint32_t smem_u32(const void* p) {
    return (uint32_t)__cvta_generic_to_shared(p);
}
__device__ __forceinline__ void ldsm_x4(uint32_t* r, uint32_t a) {
    asm volatile("ldmatrix.sync.aligned.m8n8.x4.shared.b16 {%0,%1,%2,%3}, [%4];\n"
                 : "=r"(r[0]), "=r"(r[1]), "=r"(r[2]), "=r"(r[3]) : "r"(a));
}
__device__ __forceinline__ void ldsm_x4_t(uint32_t* r, uint32_t a) {
    asm volatile("ldmatrix.sync.aligned.m8n8.x4.trans.shared.b16 {%0,%1,%2,%3}, [%4];\n"
                 : "=r"(r[0]), "=r"(r[1]), "=r"(r[2]), "=r"(r[3]) : "r"(a));
}
__device__ __forceinline__ void mma_bf16(float* d, const uint32_t* a, uint32_t b0, uint32_t b1) {
    asm volatile(
        "mma.sync.aligned.m16n8k16.row.col.f32.bf16.bf16.f32 "
        "{%0,%1,%2,%3}, {%4,%5,%6,%7}, {%8,%9}, {%0,%1,%2,%3};\n"
        : "+f"(d[0]), "+f"(d[1]), "+f"(d[2]), "+f"(d[3])
        : "r"(a[0]), "r"(a[1]), "r"(a[2]), "r"(a[3]), "r"(b0), "r"(b1));
}

// ---------------- bf16-split tensor-core GEMM: C = A @ W ----------------
// Block tile 128x128, 256 threads (8 warps, 4x2), warp tile 32x64.
// C = Ah*Wh + Ah*Wl + Al*Wh  (fp32 accumulate)
#define KC 32
__global__ __launch_bounds__(256) void gemm_bf16_kernel(
    const __nv_bfloat16* __restrict__ Ah, const __nv_bfloat16* __restrict__ Al,
    const __nv_bfloat16* __restrict__ Wh, const __nv_bfloat16* __restrict__ Wl,
    float* __restrict__ C, int M)
{
    __shared__ __nv_bfloat16 sAh[128][KC + 8];
    __shared__ __nv_bfloat16 sAl[128][KC + 8];
    __shared__ __nv_bfloat16 sWh[KC][HH + 8];
    __shared__ __nv_bfloat16 sWl[KC][HH + 8];

    int tid = threadIdx.x;
    int wid = tid >> 5, lane = tid & 31;
    int wm = wid & 3, wn = wid >> 2;
    int m0 = blockIdx.x * 128;

    float d[2][8][4];
    #pragma unroll
    for (int a = 0; a < 2; a++)
        #pragma unroll
        for (int b = 0; b < 8; b++)
            #pragma unroll
            for (int c = 0; c < 4; c++) d[a][b][c] = 0.0f;

    for (int k0 = 0; k0 < HH; k0 += KC) {
        #pragma unroll
        for (int it = 0; it < 2; it++) {
            int slot = tid + it * 256;       // 512 slots: 128 rows x 4 uint4
            int row = slot >> 2;
            int q = slot & 3;
            int m = m0 + row;
            uint4 vh = make_uint4(0,0,0,0), vl = make_uint4(0,0,0,0);
            if (m < M) {
                vh = *(const uint4*)&Ah[(size_t)m * HH + k0 + q * 8];
                vl = *(const uint4*)&Al[(size_t)m * HH + k0 + q * 8];
            }
            *(uint4*)&sAh[row][q * 8] = vh;
            *(uint4*)&sAl[row][q * 8] = vl;
        }
        #pragma unroll
        for (int it = 0; it < 2; it++) {
            int slot = tid + it * 256;       // 512 slots: 32 rows x 16 uint4
            int row = slot >> 4;
            int q = slot & 15;
            *(uint4*)&sWh[row][q * 8] = *(const uint4*)&Wh[(k0 + row) * HH + q * 8];
            *(uint4*)&sWl[row][q * 8] = *(const uint4*)&Wl[(k0 + row) * HH + q * 8];
        }
        __syncthreads();

        #pragma unroll
        for (int kk = 0; kk < KC; kk += 16) {
            uint32_t ah[2][4], al[2][4];
            #pragma unroll
            for (int mi = 0; mi < 2; mi++) {
                int r = wm * 32 + mi * 16 + (lane & 15);
                int c = kk + (lane >> 4) * 8;
                ldsm_x4(ah[mi], smem_u32(&sAh[r][c]));
                ldsm_x4(al[mi], smem_u32(&sAl[r][c]));
            }
            #pragma unroll
            for (int ni = 0; ni < 4; ni++) {
                uint32_t bh[4], bl[4];
                int rk = kk + (lane & 15);
                int cn = wn * 64 + ni * 16 + (lane >> 4) * 8;
                ldsm_x4_t(bh, smem_u32(&sWh[rk][cn]));
                ldsm_x4_t(bl, smem_u32(&sWl[rk][cn]));
                #pragma unroll
                for (int mi = 0; mi < 2; mi++) {
                    #pragma unroll
                    for (int h = 0; h < 2; h++) {
                        int nj = ni * 2 + h;
                        mma_bf16(d[mi][nj], ah[mi], bh[h*2], bh[h*2+1]);
                        mma_bf16(d[mi][nj], ah[mi], bl[h*2], bl[h*2+1]);
                        mma_bf16(d[mi][nj], al[mi], bh[h*2], bh[h*2+1]);
                    }
                }
            }
        }
        __syncthreads();
    }

    // epilogue: C frag (m16n8): c0,c1 at (lane/4, (lane%3)*2...) rows, c2,c3 at +8
    #pragma unroll
    for (int mi = 0; mi < 2; mi++) {
        #pragma unroll
        for (int nj = 0; nj < 8; nj++) {
            int col = wn * 64 + nj * 8 + (lane & 3) * 2;
            int r0 = m0 + wm * 32 + mi * 16 + (lane >> 2);
            if (r0 < M)
                *(float2*)&C[(size_t)r0 * HH + col] = make_float2(d[mi][nj][0], d[mi][nj][1]);
            int r1 = r0 + 8;
            if (r1 < M)
                *(float2*)&C[(size_t)r1 * HH + col] = make_float2(d[mi][nj][2], d[mi][nj][3]);
        }
    }
}

// ---------------- aggregation + bias + relu (+ bf16 split or pool) ----------------
__global__ void agg_kernel(const float* __restrict__ h,
                           const float* __restrict__ bias,
                           int do_pool,
                           const void* __restrict__ batch_idx,
                           float* __restrict__ pool)
{
    int warp = (blockIdx.x * blockDim.x + threadIdx.x) >> 5;
    int lane = threadIdx.x & 31;
    if (warp >= NN) return;
    int n = warp;

    float dn = g_dis[n];
    float self = dn * dn;

    float4 acc = *reinterpret_cast<const float4*>(&h[(size_t)n * HH + lane * 4]);
    acc.x *= self; acc.y *= self; acc.z *= self; acc.w *= self;

    int s0 = g_row_off[n];
    int s1 = g_row_off[n + 1];
    for (int e = s0; e < s1; e++) {
        int   s   = g_src_sorted[e];
        float nrm = g_norm_sorted[e];
        float4 v  = *reinterpret_cast<const float4*>(&h[(size_t)s * HH + lane * 4]);
        acc.x += v.x * nrm;
        acc.y += v.y * nrm;
        acc.z += v.z * nrm;
        acc.w += v.w * nrm;
    }

    float4 bb = *reinterpret_cast<const float4*>(&bias[lane * 4]);
    acc.x = fmaxf(acc.x + bb.x, 0.0f);
    acc.y = fmaxf(acc.y + bb.y, 0.0f);
    acc.z = fmaxf(acc.z + bb.z, 0.0f);
    acc.w = fmaxf(acc.w + bb.w, 0.0f);

    if (!do_pool) {
        __nv_bfloat16 h0,h1,h2,h3,l0,l1,l2,l3;
        split_bf16(acc.x,h0,l0); split_bf16(acc.y,h1,l1);
        split_bf16(acc.z,h2,l2); split_bf16(acc.w,h3,l3);
        __nv_bfloat162* ph = (__nv_bfloat162*)&g_ah[(size_t)n * HH + lane * 4];
        __nv_bfloat162* pl = (__nv_bfloat162*)&g_al[(size_t)n * HH + lane * 4];
        ph[0] = __nv_bfloat162{h0,h1}; ph[1] = __nv_bfloat162{h2,h3};
        pl[0] = __nv_bfloat162{l0,l1}; pl[1] = __nv_bfloat162{l2,l3};
    } else {
        int g = idx_at(batch_idx, n);
        float* p = &pool[g * HH + lane * 4];
        atomicAdd(p + 0, acc.x);
        atomicAdd(p + 1, acc.y);
        atomicAdd(p + 2, acc.z);
        atomicAdd(p + 3, acc.w);
        if (lane == 0) atomicAdd(&g_cnt[g], 1.0f);
    }
}

__global__ void divide_kernel(float* __restrict__ out) {
    int i = blockIdx.x * blockDim.x + threadIdx.x;
    if (i >= GG * HH) return;
    out[i] /= fmaxf(g_cnt[i >> 7], 1.0f);
}

// ---------------- launch ----------------
extern "C" void kernel_launch(void* const* d_in, const int* in_sizes, int n_in,
                              void* d_out, int out_size)
{
    const float* x    = (const float*)d_in[0];
    const float* W1   = (const float*)d_in[1];
    const float* b1   = (const float*)d_in[2];
    const float* W2   = (const float*)d_in[3];
    const float* b2   = (const float*)d_in[4];
    const float* W3   = (const float*)d_in[5];
    const float* b3   = (const float*)d_in[6];
    const void*  ei   = d_in[7];
    const void*  bidx = d_in[8];
    float* out = (float*)d_out;

    float *tmp; __nv_bfloat16 *ah, *al, *wh, *wl;
    cudaGetSymbolAddress((void**)&tmp, g_tmp);
    cudaGetSymbolAddress((void**)&ah,  g_ah);
    cudaGetSymbolAddress((void**)&al,  g_al);
    cudaGetSymbolAddress((void**)&wh,  g_wh);
    cudaGetSymbolAddress((void**)&wl,  g_wl);
    (void)in_sizes; (void)n_in; (void)out_size;

    const int T = 256;

    detect_kernel<<<1, 1>>>((const int*)ei);
    init_kernel<<<(NN + T - 1) / T, T>>>(out);
    deg_kernel<<<(EE + T - 1) / T, T>>>(ei);
    dis_kernel<<<(NN + T - 1) / T, T>>>();
    scan1_kernel<<<NP, SCAN_B>>>();
    scan2_kernel<<<1, 128>>>();
    scan3_kernel<<<NP, SCAN_B>>>();
    fill_kernel<<<(EE + T - 1) / T, T>>>(ei);
    convertw_kernel<<<(3 * HH * HH + T - 1) / T, T>>>(W1, W2, W3);
    convertx_kernel<<<(NN * HH / 4 + T - 1) / T, T>>>(x);

    int gemm_blocks = (NN + 127) / 128;
    int agg_blocks  = (NN * 32 + T - 1) / T;

    gemm_bf16_kernel<<<gemm_blocks, 256>>>(ah, al, wh + 0 * HH * HH, wl + 0 * HH * HH, tmp, NN);
    agg_kernel<<<agg_blocks, T>>>(tmp, b1, 0, bidx, out);

    gemm_bf16_kernel<<<gemm_blocks, 256>>>(ah, al, wh + 1 * HH * HH, wl + 1 * HH * HH, tmp, NN);
    agg_kernel<<<agg_blocks, T>>>(tmp, b2, 0, bidx, out);

    gemm_bf16_kernel<<<gemm_blocks, 256>>>(ah, al, wh + 2 * HH * HH, wl + 2 * HH * HH, tmp, NN);
    agg_kernel<<<agg_blocks, T>>>(tmp, b3, 1, bidx, out);

    divide_kernel<<<(GG * HH + T - 1) / T, T>>>(out);
}

// round 6
// speedup vs baseline: 1.7591x; 1.0633x over previous
#include <cuda_runtime.h>
#include <cuda_bf16.h>
#include <cuda_fp16.h>
#include <cstdint>

#define NN 50000
#define EE 600000
#define GG 256
#define HH 128
#define SCAN_B 512
#define NP ((NN + SCAN_B - 1) / SCAN_B)

typedef __nv_bfloat16 bf16;

// ---------------- scratch ----------------
__device__ __half g_tmp[NN * HH];     // GEMM output (fp16)
__device__ bf16  g_ah[NN * HH];
__device__ bf16  g_al[NN * HH];
__device__ bf16  g_wh[3 * HH * HH];   // row-major [k][n] (NO transpose)
__device__ bf16  g_wl[3 * HH * HH];
__device__ float g_dis[NN];
__device__ int   g_deg[NN];
__device__ int   g_row_off[NN + 1];
__device__ int   g_fill[NN];
__device__ int   g_src_sorted[EE];
__device__ float g_norm_sorted[EE];
__device__ float g_cnt[GG];
__device__ int   g_part[NP];
__device__ int   g_idx64;

__device__ __forceinline__ int idx_at(const void* p, long long i) {
    if (g_idx64) return (int)((const long long*)p)[i];
    return ((const int*)p)[i];
}

// ---------------- init (+ dtype detect) ----------------
__global__ void init_kernel(float* __restrict__ out, const int* __restrict__ ei_raw) {
    int i = blockIdx.x * blockDim.x + threadIdx.x;
    if (i == 0) {
        int all_zero = 1;
        for (int k = 1; k < 64; k += 2)
            if (ei_raw[k] != 0) all_zero = 0;
        g_idx64 = all_zero;
    }
    if (i < NN) { g_deg[i] = 0; g_fill[i] = 0; }
    if (i < GG * HH) out[i] = 0.0f;
    if (i < GG) g_cnt[i] = 0.0f;
}

__global__ void deg_kernel(const void* __restrict__ edge_index) {
    int e = blockIdx.x * blockDim.x + threadIdx.x;
    if (e >= EE) return;
    atomicAdd(&g_deg[idx_at(edge_index, (long long)EE + e)], 1);
}

// ---------------- fp32 -> bf16 hi/lo ----------------
__device__ __forceinline__ void split_bf16(float v, bf16& h, bf16& l) {
    h = __float2bfloat16_rn(v);
    l = __float2bfloat16_rn(v - __bfloat162float(h));
}

// ---------------- merged convert: x split + W split (row-major, NO transpose) ----------------
__global__ void convert_kernel(const float* __restrict__ x,
                               const float* __restrict__ W1,
                               const float* __restrict__ W2,
                               const float* __restrict__ W3) {
    int i = blockIdx.x * blockDim.x + threadIdx.x;
    if (i < NN * HH / 4) {
        float4 v = ((const float4*)x)[i];
        bf16 h0,h1,h2,h3,l0,l1,l2,l3;
        split_bf16(v.x,h0,l0); split_bf16(v.y,h1,l1);
        split_bf16(v.z,h2,l2); split_bf16(v.w,h3,l3);
        __nv_bfloat162* ph = (__nv_bfloat162*)&g_ah[i*4];
        __nv_bfloat162* pl = (__nv_bfloat162*)&g_al[i*4];
        ph[0] = __nv_bfloat162{h0,h1}; ph[1] = __nv_bfloat162{h2,h3};
        pl[0] = __nv_bfloat162{l0,l1}; pl[1] = __nv_bfloat162{l2,l3};
    }
    if (i < 3 * HH * HH) {
        int which = i >> 14;
        int j = i & (HH * HH - 1);
        const float* W = (which == 0) ? W1 : (which == 1) ? W2 : W3;
        bf16 h, l;
        split_bf16(W[j], h, l);          // keep [k][n] row-major (matches GEMM)
        g_wh[i] = h; g_wl[i] = l;
    }
}

// ---------------- scan phase 1 (+ deg_inv_sqrt fused) ----------------
__global__ void scan1_kernel() {
    int b = blockIdx.x, t = threadIdx.x;
    int i = b * SCAN_B + t;
    int lane = t & 31, w = t >> 5;
    int v = (i < NN) ? g_deg[i] : 0;
    if (i < NN) g_dis[i] = rsqrtf((float)v + 1.0f);
    int x = v;
    #pragma unroll
    for (int off = 1; off < 32; off <<= 1) {
        int y = __shfl_up_sync(0xffffffffu, x, off);
        if (lane >= off) x += y;
    }
    __shared__ int wsum[16];
    if (lane == 31) wsum[w] = x;
    __syncthreads();
    if (w == 0) {
        int s = (lane < 16) ? wsum[lane] : 0;
        #pragma unroll
        for (int off = 1; off < 16; off <<= 1) {
            int y = __shfl_up_sync(0xffffffffu, s, off);
            if (lane >= off) s += y;
        }
        if (lane < 16) wsum[lane] = s;
    }
    __syncthreads();
    int inc = x + ((w > 0) ? wsum[w - 1] : 0);
    if (i < NN) g_row_off[i + 1] = inc;
    if (t == SCAN_B - 1) g_part[b] = inc;
}

__global__ void scan2_kernel() {
    int t = threadIdx.x;
    int lane = t & 31, w = t >> 5;
    int x = (t < NP) ? g_part[t] : 0;
    #pragma unroll
    for (int off = 1; off < 32; off <<= 1) {
        int y = __shfl_up_sync(0xffffffffu, x, off);
        if (lane >= off) x += y;
    }
    __shared__ int wsum[4];
    if (lane == 31) wsum[w] = x;
    __syncthreads();
    if (w == 0 && lane < 4) {
        int s = wsum[lane];
        #pragma unroll
        for (int off = 1; off < 4; off <<= 1) {
            int y = __shfl_up_sync(0x0000000fu, s, off);
            if (lane >= off) s += y;
        }
        wsum[lane] = s;
    }
    __syncthreads();
    int inc = x + ((w > 0) ? wsum[w - 1] : 0);
    if (t < NP) g_part[t] = inc;
}

__global__ void scan3_kernel() {
    int b = blockIdx.x, t = threadIdx.x;
    int i = b * SCAN_B + t;
    if (b > 0 && i < NN) g_row_off[i + 1] += g_part[b - 1];
    if (i == 0) g_row_off[0] = 0;
}

// ---------------- CSR fill ----------------
__global__ void fill_kernel(const void* __restrict__ edge_index) {
    int e = blockIdx.x * blockDim.x + threadIdx.x;
    if (e >= EE) return;
    int s = idx_at(edge_index, e);
    int d = idx_at(edge_index, (long long)EE + e);
    int p = g_row_off[d] + atomicAdd(&g_fill[d], 1);
    g_src_sorted[p]  = s;
    g_norm_sorted[p] = g_dis[s] * g_dis[d];
}

// ---------------- mma helpers ----------------
__device__ __forceinline__ uint32_t smem_u32(const void* p) {
    return (uint32_t)__cvta_generic_to_shared(p);
}
__device__ __forceinline__ void ldsm_x4(uint32_t* r, uint32_t a) {
    asm volatile("ldmatrix.sync.aligned.m8n8.x4.shared.b16 {%0,%1,%2,%3}, [%4];\n"
                 : "=r"(r[0]), "=r"(r[1]), "=r"(r[2]), "=r"(r[3]) : "r"(a));
}
__device__ __forceinline__ void ldsm_x4_t(uint32_t* r, uint32_t a) {
    asm volatile("ldmatrix.sync.aligned.m8n8.x4.trans.shared.b16 {%0,%1,%2,%3}, [%4];\n"
                 : "=r"(r[0]), "=r"(r[1]), "=r"(r[2]), "=r"(r[3]) : "r"(a));
}
__device__ __forceinline__ void mma_bf16(float* d, const uint32_t* a, uint32_t b0, uint32_t b1) {
    asm volatile(
        "mma.sync.aligned.m16n8k16.row.col.f32.bf16.bf16.f32 "
        "{%0,%1,%2,%3}, {%4,%5,%6,%7}, {%8,%9}, {%0,%1,%2,%3};\n"
        : "+f"(d[0]), "+f"(d[1]), "+f"(d[2]), "+f"(d[3])
        : "r"(a[0]), "r"(a[1]), "r"(a[2]), "r"(a[3]), "r"(b0), "r"(b1));
}

// ---------------- bf16-split tensor-core GEMM, fp16 output ----------------
#define KC 32
__global__ __launch_bounds__(256) void gemm_bf16_kernel(
    const bf16* __restrict__ Ah, const bf16* __restrict__ Al,
    const bf16* __restrict__ Wh, const bf16* __restrict__ Wl,
    __half* __restrict__ C, int M)
{
    __shared__ bf16 sAh[128][KC + 8];
    __shared__ bf16 sAl[128][KC + 8];
    __shared__ bf16 sWh[KC][HH + 8];
    __shared__ bf16 sWl[KC][HH + 8];

    int tid = threadIdx.x;
    int wid = tid >> 5, lane = tid & 31;
    int wm = wid & 3, wn = wid >> 2;
    int m0 = blockIdx.x * 128;

    float d[2][8][4];
    #pragma unroll
    for (int a = 0; a < 2; a++)
        #pragma unroll
        for (int b = 0; b < 8; b++)
            #pragma unroll
            for (int c = 0; c < 4; c++) d[a][b][c] = 0.0f;

    for (int k0 = 0; k0 < HH; k0 += KC) {
        #pragma unroll
        for (int it = 0; it < 2; it++) {
            int slot = tid + it * 256;
            int row = slot >> 2;
            int q = slot & 3;
            int m = m0 + row;
            uint4 vh = make_uint4(0,0,0,0), vl = make_uint4(0,0,0,0);
            if (m < M) {
                vh = *(const uint4*)&Ah[(size_t)m * HH + k0 + q * 8];
                vl = *(const uint4*)&Al[(size_t)m * HH + k0 + q * 8];
            }
            *(uint4*)&sAh[row][q * 8] = vh;
            *(uint4*)&sAl[row][q * 8] = vl;
        }
        #pragma unroll
        for (int it = 0; it < 2; it++) {
            int slot = tid + it * 256;
            int row = slot >> 4;
            int q = slot & 15;
            *(uint4*)&sWh[row][q * 8] = *(const uint4*)&Wh[(k0 + row) * HH + q * 8];
            *(uint4*)&sWl[row][q * 8] = *(const uint4*)&Wl[(k0 + row) * HH + q * 8];
        }
        __syncthreads();

        #pragma unroll
        for (int kk = 0; kk < KC; kk += 16) {
            uint32_t ah[2][4], al[2][4];
            #pragma unroll
            for (int mi = 0; mi < 2; mi++) {
                int r = wm * 32 + mi * 16 + (lane & 15);
                int c = kk + (lane >> 4) * 8;
                ldsm_x4(ah[mi], smem_u32(&sAh[r][c]));
                ldsm_x4(al[mi], smem_u32(&sAl[r][c]));
            }
            #pragma unroll
            for (int ni = 0; ni < 4; ni++) {
                uint32_t bh[4], bl[4];
                int rk = kk + (lane & 15);
                int cn = wn * 64 + ni * 16 + (lane >> 4) * 8;
                ldsm_x4_t(bh, smem_u32(&sWh[rk][cn]));
                ldsm_x4_t(bl, smem_u32(&sWl[rk][cn]));
                #pragma unroll
                for (int mi = 0; mi < 2; mi++) {
                    #pragma unroll
                    for (int h = 0; h < 2; h++) {
                        int nj = ni * 2 + h;
                        mma_bf16(d[mi][nj], ah[mi], bh[h*2], bh[h*2+1]);
                        mma_bf16(d[mi][nj], ah[mi], bl[h*2], bl[h*2+1]);
                        mma_bf16(d[mi][nj], al[mi], bh[h*2], bh[h*2+1]);
                    }
                }
            }
        }
        __syncthreads();
    }

    #pragma unroll
    for (int mi = 0; mi < 2; mi++) {
        #pragma unroll
        for (int nj = 0; nj < 8; nj++) {
            int col = wn * 64 + nj * 8 + (lane & 3) * 2;
            int r0 = m0 + wm * 32 + mi * 16 + (lane >> 2);
            if (r0 < M)
                *(__half2*)&C[(size_t)r0 * HH + col] = __floats2half2_rn(d[mi][nj][0], d[mi][nj][1]);
            int r1 = r0 + 8;
            if (r1 < M)
                *(__half2*)&C[(size_t)r1 * HH + col] = __floats2half2_rn(d[mi][nj][2], d[mi][nj][3]);
        }
    }
}

// ---------------- aggregation (fp16 gather) + bias + relu ----------------
__device__ __forceinline__ float4 ld_row_h(const __half* h, int node, int lane) {
    const __half2* p = (const __half2*)&h[(size_t)node * HH + lane * 4];
    float2 a = __half22float2(p[0]);
    float2 b = __half22float2(p[1]);
    return make_float4(a.x, a.y, b.x, b.y);
}

__global__ void agg_kernel(const __half* __restrict__ h,
                           const float* __restrict__ bias,
                           int do_pool,
                           const void* __restrict__ batch_idx,
                           float* __restrict__ pool)
{
    int warp = (blockIdx.x * blockDim.x + threadIdx.x) >> 5;
    int lane = threadIdx.x & 31;
    if (warp >= NN) return;
    int n = warp;

    float dn = g_dis[n];
    float self = dn * dn;

    float4 acc = ld_row_h(h, n, lane);
    acc.x *= self; acc.y *= self; acc.z *= self; acc.w *= self;

    int e  = g_row_off[n];
    int s1 = g_row_off[n + 1];
    for (; e + 3 < s1; e += 4) {
        int   sA = g_src_sorted[e],   sB = g_src_sorted[e+1];
        int   sC = g_src_sorted[e+2], sD = g_src_sorted[e+3];
        float nA = g_norm_sorted[e],   nB = g_norm_sorted[e+1];
        float nC = g_norm_sorted[e+2], nD = g_norm_sorted[e+3];
        float4 vA = ld_row_h(h, sA, lane);
        float4 vB = ld_row_h(h, sB, lane);
        float4 vC = ld_row_h(h, sC, lane);
        float4 vD = ld_row_h(h, sD, lane);
        acc.x += vA.x*nA + vB.x*nB + vC.x*nC + vD.x*nD;
        acc.y += vA.y*nA + vB.y*nB + vC.y*nC + vD.y*nD;
        acc.z += vA.z*nA + vB.z*nB + vC.z*nC + vD.z*nD;
        acc.w += vA.w*nA + vB.w*nB + vC.w*nC + vD.w*nD;
    }
    for (; e < s1; e++) {
        int   s   = g_src_sorted[e];
        float nrm = g_norm_sorted[e];
        float4 v  = ld_row_h(h, s, lane);
        acc.x += v.x * nrm; acc.y += v.y * nrm;
        acc.z += v.z * nrm; acc.w += v.w * nrm;
    }

    float4 bb = *reinterpret_cast<const float4*>(&bias[lane * 4]);
    acc.x = fmaxf(acc.x + bb.x, 0.0f);
    acc.y = fmaxf(acc.y + bb.y, 0.0f);
    acc.z = fmaxf(acc.z + bb.z, 0.0f);
    acc.w = fmaxf(acc.w + bb.w, 0.0f);

    if (!do_pool) {
        bf16 h0,h1,h2,h3,l0,l1,l2,l3;
        split_bf16(acc.x,h0,l0); split_bf16(acc.y,h1,l1);
        split_bf16(acc.z,h2,l2); split_bf16(acc.w,h3,l3);
        __nv_bfloat162* ph = (__nv_bfloat162*)&g_ah[(size_t)n * HH + lane * 4];
        __nv_bfloat162* pl = (__nv_bfloat162*)&g_al[(size_t)n * HH + lane * 4];
        ph[0] = __nv_bfloat162{h0,h1}; ph[1] = __nv_bfloat162{h2,h3};
        pl[0] = __nv_bfloat162{l0,l1}; pl[1] = __nv_bfloat162{l2,l3};
    } else {
        int g = idx_at(batch_idx, n);
        float* p = &pool[g * HH + lane * 4];
        atomicAdd(p + 0, acc.x);
        atomicAdd(p + 1, acc.y);
        atomicAdd(p + 2, acc.z);
        atomicAdd(p + 3, acc.w);
        if (lane == 0) atomicAdd(&g_cnt[g], 1.0f);
    }
}

__global__ void divide_kernel(float* __restrict__ out) {
    int i = blockIdx.x * blockDim.x + threadIdx.x;
    if (i >= GG * HH) return;
    out[i] /= fmaxf(g_cnt[i >> 7], 1.0f);
}

// ---------------- launch ----------------
extern "C" void kernel_launch(void* const* d_in, const int* in_sizes, int n_in,
                              void* d_out, int out_size)
{
    const float* x    = (const float*)d_in[0];
    const float* W1   = (const float*)d_in[1];
    const float* b1   = (const float*)d_in[2];
    const float* W2   = (const float*)d_in[3];
    const float* b2   = (const float*)d_in[4];
    const float* W3   = (const float*)d_in[5];
    const float* b3   = (const float*)d_in[6];
    const void*  ei   = d_in[7];
    const void*  bidx = d_in[8];
    float* out = (float*)d_out;

    __half *tmp; bf16 *ah, *al, *wh, *wl;
    cudaGetSymbolAddress((void**)&tmp, g_tmp);
    cudaGetSymbolAddress((void**)&ah,  g_ah);
    cudaGetSymbolAddress((void**)&al,  g_al);
    cudaGetSymbolAddress((void**)&wh,  g_wh);
    cudaGetSymbolAddress((void**)&wl,  g_wl);
    (void)in_sizes; (void)n_in; (void)out_size;

    const int T = 256;
    int gemm_blocks = (NN + 127) / 128;
    int agg_blocks  = (NN * 32 + T - 1) / T;

    // ordered so launch index 5 (ncu -s 5) is gemm1
    init_kernel<<<(NN + T - 1) / T, T>>>(out, (const int*)ei);          // 0
    convert_kernel<<<(NN * HH / 4 + T - 1) / T, T>>>(x, W1, W2, W3);    // 1
    deg_kernel<<<(EE + T - 1) / T, T>>>(ei);                            // 2
    scan1_kernel<<<NP, SCAN_B>>>();                                     // 3
    scan2_kernel<<<1, 128>>>();                                         // 4
    gemm_bf16_kernel<<<gemm_blocks, 256>>>(ah, al, wh, wl, tmp, NN);    // 5 (profiled)
    scan3_kernel<<<NP, SCAN_B>>>();                                     // 6
    fill_kernel<<<(EE + T - 1) / T, T>>>(ei);                           // 7
    agg_kernel<<<agg_blocks, T>>>(tmp, b1, 0, bidx, out);               // 8

    gemm_bf16_kernel<<<gemm_blocks, 256>>>(ah, al, wh + HH*HH, wl + HH*HH, tmp, NN);
    agg_kernel<<<agg_blocks, T>>>(tmp, b2, 0, bidx, out);

    gemm_bf16_kernel<<<gemm_blocks, 256>>>(ah, al, wh + 2*HH*HH, wl + 2*HH*HH, tmp, NN);
    agg_kernel<<<agg_blocks, T>>>(tmp, b3, 1, bidx, out);

    divide_kernel<<<(GG * HH + T - 1) / T, T>>>(out);
}

// round 8
// speedup vs baseline: 1.9360x; 1.1006x over previous
#include <cuda_runtime.h>
#include <cuda_bf16.h>
#include <cuda_fp16.h>
#include <cstdint>

#define NN 50000
#define EE 600000
#define GG 256
#define HH 128
#define SCAN_B 512
#define NP ((NN + SCAN_B - 1) / SCAN_B)

// ---------------- scratch ----------------
__device__ __half g_x16[NN * HH];     // fp16 activations (GEMM input)
__device__ __half g_tmp[NN * HH];     // fp16 GEMM output
__device__ __half g_wh[3 * HH * HH];  // fp16 weights hi  [k][n]
__device__ __half g_wl[3 * HH * HH];  // fp16 weights lo  [k][n]
__device__ float g_dis[NN];
__device__ int   g_deg[NN];
__device__ int   g_row_off[NN + 1];   // block-local inclusive scan (scan3 folded into readers)
__device__ int   g_fill[NN];
__device__ int   g_src_sorted[EE];
__device__ float g_norm_sorted[EE];
__device__ float g_cnt[GG];
__device__ int   g_part[NP];          // inclusive partials per scan block
__device__ int   g_idx64;

__device__ __forceinline__ int idx_at(const void* p, long long i) {
    if (g_idx64) return (int)((const long long*)p)[i];
    return ((const int*)p)[i];
}

// final exclusive CSR offset for node j (applies cross-block partial inline)
__device__ __forceinline__ int roff(int j) {
    if (j == 0) return 0;
    int b = (j - 1) / SCAN_B;
    int v = g_row_off[j];
    return (b > 0) ? v + g_part[b - 1] : v;
}

// ---------------- init (+ dtype detect) ----------------
__global__ void init_kernel(float* __restrict__ out, const int* __restrict__ ei_raw) {
    int i = blockIdx.x * blockDim.x + threadIdx.x;
    if (i == 0) {
        int all_zero = 1;
        for (int k = 1; k < 64; k += 2)
            if (ei_raw[k] != 0) all_zero = 0;
        g_idx64 = all_zero;
    }
    if (i < NN) { g_deg[i] = 0; g_fill[i] = 0; }
    if (i < GG * HH) out[i] = 0.0f;
    if (i < GG) g_cnt[i] = 0.0f;
}

// ---------------- merged: x->fp16, W->fp16 hi/lo, degree histogram ----------------
__global__ void cvt_deg_kernel(const float* __restrict__ x,
                               const float* __restrict__ W1,
                               const float* __restrict__ W2,
                               const float* __restrict__ W3,
                               const void* __restrict__ edge_index) {
    int i = blockIdx.x * blockDim.x + threadIdx.x;
    if (i < NN * HH / 4) {
        float4 v = ((const float4*)x)[i];
        __half2* p = (__half2*)&g_x16[i * 4];
        p[0] = __floats2half2_rn(v.x, v.y);
        p[1] = __floats2half2_rn(v.z, v.w);
    }
    if (i < 3 * HH * HH) {
        int which = i >> 14;
        int j = i & (HH * HH - 1);
        const float* W = (which == 0) ? W1 : (which == 1) ? W2 : W3;
        float w = W[j];
        __half h = __float2half_rn(w);
        g_wh[i] = h;
        g_wl[i] = __float2half_rn(w - __half2float(h));
    }
    if (i < EE) {
        atomicAdd(&g_deg[idx_at(edge_index, (long long)EE + i)], 1);
    }
}

// ---------------- scan phase 1 (+ deg_inv_sqrt fused) ----------------
__global__ void scan1_kernel() {
    int b = blockIdx.x, t = threadIdx.x;
    int i = b * SCAN_B + t;
    int lane = t & 31, w = t >> 5;
    int v = (i < NN) ? g_deg[i] : 0;
    if (i < NN) g_dis[i] = rsqrtf((float)v + 1.0f);
    int x = v;
    #pragma unroll
    for (int off = 1; off < 32; off <<= 1) {
        int y = __shfl_up_sync(0xffffffffu, x, off);
        if (lane >= off) x += y;
    }
    __shared__ int wsum[16];
    if (lane == 31) wsum[w] = x;
    __syncthreads();
    if (w == 0) {
        int s = (lane < 16) ? wsum[lane] : 0;
        #pragma unroll
        for (int off = 1; off < 16; off <<= 1) {
            int y = __shfl_up_sync(0xffffffffu, s, off);
            if (lane >= off) s += y;
        }
        if (lane < 16) wsum[lane] = s;
    }
    __syncthreads();
    int inc = x + ((w > 0) ? wsum[w - 1] : 0);
    if (i < NN) g_row_off[i + 1] = inc;
    if (t == SCAN_B - 1) g_part[b] = inc;
}

__global__ void scan2_kernel() {
    int t = threadIdx.x;
    int lane = t & 31, w = t >> 5;
    int x = (t < NP) ? g_part[t] : 0;
    #pragma unroll
    for (int off = 1; off < 32; off <<= 1) {
        int y = __shfl_up_sync(0xffffffffu, x, off);
        if (lane >= off) x += y;
    }
    __shared__ int wsum[4];
    if (lane == 31) wsum[w] = x;
    __syncthreads();
    if (w == 0 && lane < 4) {
        int s = wsum[lane];
        #pragma unroll
        for (int off = 1; off < 4; off <<= 1) {
            int y = __shfl_up_sync(0x0000000fu, s, off);
            if (lane >= off) s += y;
        }
        wsum[lane] = s;
    }
    __syncthreads();
    int inc = x + ((w > 0) ? wsum[w - 1] : 0);
    if (t < NP) g_part[t] = inc;
}

// ---------------- CSR fill (scan3 applied inline via roff) ----------------
__global__ void fill_kernel(const void* __restrict__ edge_index) {
    int e = blockIdx.x * blockDim.x + threadIdx.x;
    if (e >= EE) return;
    int s = idx_at(edge_index, e);
    int d = idx_at(edge_index, (long long)EE + e);
    int p = roff(d) + atomicAdd(&g_fill[d], 1);
    g_src_sorted[p]  = s;
    g_norm_sorted[p] = g_dis[s] * g_dis[d];
}

// ---------------- mma helpers ----------------
__device__ __forceinline__ uint32_t smem_u32(const void* p) {
    return (uint32_t)__cvta_generic_to_shared(p);
}
__device__ __forceinline__ void ldsm_x4(uint32_t* r, uint32_t a) {
    asm volatile("ldmatrix.sync.aligned.m8n8.x4.shared.b16 {%0,%1,%2,%3}, [%4];\n"
                 : "=r"(r[0]), "=r"(r[1]), "=r"(r[2]), "=r"(r[3]) : "r"(a));
}
__device__ __forceinline__ void ldsm_x4_t(uint32_t* r, uint32_t a) {
    asm volatile("ldmatrix.sync.aligned.m8n8.x4.trans.shared.b16 {%0,%1,%2,%3}, [%4];\n"
                 : "=r"(r[0]), "=r"(r[1]), "=r"(r[2]), "=r"(r[3]) : "r"(a));
}
__device__ __forceinline__ void mma_f16(float* d, const uint32_t* a, uint32_t b0, uint32_t b1) {
    asm volatile(
        "mma.sync.aligned.m16n8k16.row.col.f32.f16.f16.f32 "
        "{%0,%1,%2,%3}, {%4,%5,%6,%7}, {%8,%9}, {%0,%1,%2,%3};\n"
        : "+f"(d[0]), "+f"(d[1]), "+f"(d[2]), "+f"(d[3])
        : "r"(a[0]), "r"(a[1]), "r"(a[2]), "r"(a[3]), "r"(b0), "r"(b1));
}

// ---------------- fp16 2-term tensor-core GEMM: C = A*(Wh + Wl) ----------------
#define KC 32
__global__ __launch_bounds__(256) void gemm_f16_kernel(
    const __half* __restrict__ A,
    const __half* __restrict__ Wh, const __half* __restrict__ Wl,
    __half* __restrict__ C, int M)
{
    __shared__ __half sA [128][KC + 8];
    __shared__ __half sWh[KC][HH + 8];
    __shared__ __half sWl[KC][HH + 8];

    int tid = threadIdx.x;
    int wid = tid >> 5, lane = tid & 31;
    int wm = wid & 3, wn = wid >> 2;
    int m0 = blockIdx.x * 128;

    float d[2][8][4];
    #pragma unroll
    for (int a = 0; a < 2; a++)
        #pragma unroll
        for (int b = 0; b < 8; b++)
            #pragma unroll
            for (int c = 0; c < 4; c++) d[a][b][c] = 0.0f;

    for (int k0 = 0; k0 < HH; k0 += KC) {
        #pragma unroll
        for (int it = 0; it < 2; it++) {
            int slot = tid + it * 256;      // 512 slots: 128 rows x 4 uint4
            int row = slot >> 2;
            int q = slot & 3;
            int m = m0 + row;
            uint4 v = make_uint4(0,0,0,0);
            if (m < M) v = *(const uint4*)&A[(size_t)m * HH + k0 + q * 8];
            *(uint4*)&sA[row][q * 8] = v;
        }
        #pragma unroll
        for (int it = 0; it < 2; it++) {
            int slot = tid + it * 256;      // 512 slots: 32 rows x 16 uint4
            int row = slot >> 4;
            int q = slot & 15;
            *(uint4*)&sWh[row][q * 8] = *(const uint4*)&Wh[(k0 + row) * HH + q * 8];
            *(uint4*)&sWl[row][q * 8] = *(const uint4*)&Wl[(k0 + row) * HH + q * 8];
        }
        __syncthreads();

        #pragma unroll
        for (int kk = 0; kk < KC; kk += 16) {
            uint32_t af[2][4];
            #pragma unroll
            for (int mi = 0; mi < 2; mi++) {
                int r = wm * 32 + mi * 16 + (lane & 15);
                int c = kk + (lane >> 4) * 8;
                ldsm_x4(af[mi], smem_u32(&sA[r][c]));
            }
            #pragma unroll
            for (int ni = 0; ni < 4; ni++) {
                uint32_t bh[4], bl[4];
                int rk = kk + (lane & 15);
                int cn = wn * 64 + ni * 16 + (lane >> 4) * 8;
                ldsm_x4_t(bh, smem_u32(&sWh[rk][cn]));
                ldsm_x4_t(bl, smem_u32(&sWl[rk][cn]));
                #pragma unroll
                for (int mi = 0; mi < 2; mi++) {
                    #pragma unroll
                    for (int h = 0; h < 2; h++) {
                        int nj = ni * 2 + h;
                        mma_f16(d[mi][nj], af[mi], bh[h*2], bh[h*2+1]);
                        mma_f16(d[mi][nj], af[mi], bl[h*2], bl[h*2+1]);
                    }
                }
            }
        }
        __syncthreads();
    }

    #pragma unroll
    for (int mi = 0; mi < 2; mi++) {
        #pragma unroll
        for (int nj = 0; nj < 8; nj++) {
            int col = wn * 64 + nj * 8 + (lane & 3) * 2;
            int r0 = m0 + wm * 32 + mi * 16 + (lane >> 2);
            if (r0 < M)
                *(__half2*)&C[(size_t)r0 * HH + col] = __floats2half2_rn(d[mi][nj][0], d[mi][nj][1]);
            int r1 = r0 + 8;
            if (r1 < M)
                *(__half2*)&C[(size_t)r1 * HH + col] = __floats2half2_rn(d[mi][nj][2], d[mi][nj][3]);
        }
    }
}

// ---------------- aggregation (fp16 gather -> fp16 out / pool) ----------------
__device__ __forceinline__ float4 ld_row_h(const __half* h, int node, int lane) {
    const __half2* p = (const __half2*)&h[(size_t)node * HH + lane * 4];
    float2 a = __half22float2(p[0]);
    float2 b = __half22float2(p[1]);
    return make_float4(a.x, a.y, b.x, b.y);
}

__global__ void agg_kernel(const __half* __restrict__ h,
                           const float* __restrict__ bias,
                           __half* __restrict__ out16,
                           int do_pool,
                           const void* __restrict__ batch_idx,
                           float* __restrict__ pool)
{
    int warp = (blockIdx.x * blockDim.x + threadIdx.x) >> 5;
    int lane = threadIdx.x & 31;
    if (warp >= NN) return;
    int n = warp;

    float dn = g_dis[n];
    float self = dn * dn;

    float4 acc = ld_row_h(h, n, lane);
    acc.x *= self; acc.y *= self; acc.z *= self; acc.w *= self;

    int e  = roff(n);
    int s1 = roff(n + 1);
    for (; e + 3 < s1; e += 4) {
        int   sA = g_src_sorted[e],   sB = g_src_sorted[e+1];
        int   sC = g_src_sorted[e+2], sD = g_src_sorted[e+3];
        float nA = g_norm_sorted[e],   nB = g_norm_sorted[e+1];
        float nC = g_norm_sorted[e+2], nD = g_norm_sorted[e+3];
        float4 vA = ld_row_h(h, sA, lane);
        float4 vB = ld_row_h(h, sB, lane);
        float4 vC = ld_row_h(h, sC, lane);
        float4 vD = ld_row_h(h, sD, lane);
        acc.x += vA.x*nA + vB.x*nB + vC.x*nC + vD.x*nD;
        acc.y += vA.y*nA + vB.y*nB + vC.y*nC + vD.y*nD;
        acc.z += vA.z*nA + vB.z*nB + vC.z*nC + vD.z*nD;
        acc.w += vA.w*nA + vB.w*nB + vC.w*nC + vD.w*nD;
    }
    for (; e < s1; e++) {
        int   s   = g_src_sorted[e];
        float nrm = g_norm_sorted[e];
        float4 v  = ld_row_h(h, s, lane);
        acc.x += v.x * nrm; acc.y += v.y * nrm;
        acc.z += v.z * nrm; acc.w += v.w * nrm;
    }

    float4 bb = *reinterpret_cast<const float4*>(&bias[lane * 4]);
    acc.x = fmaxf(acc.x + bb.x, 0.0f);
    acc.y = fmaxf(acc.y + bb.y, 0.0f);
    acc.z = fmaxf(acc.z + bb.z, 0.0f);
    acc.w = fmaxf(acc.w + bb.w, 0.0f);

    if (!do_pool) {
        __half2* p = (__half2*)&out16[(size_t)n * HH + lane * 4];
        p[0] = __floats2half2_rn(acc.x, acc.y);
        p[1] = __floats2half2_rn(acc.z, acc.w);
    } else {
        int g = idx_at(batch_idx, n);
        float* p = &pool[g * HH + lane * 4];
        atomicAdd(p + 0, acc.x);
        atomicAdd(p + 1, acc.y);
        atomicAdd(p + 2, acc.z);
        atomicAdd(p + 3, acc.w);
        if (lane == 0) atomicAdd(&g_cnt[g], 1.0f);
    }
}

__global__ void divide_kernel(float* __restrict__ out) {
    int i = blockIdx.x * blockDim.x + threadIdx.x;
    if (i >= GG * HH) return;
    out[i] /= fmaxf(g_cnt[i >> 7], 1.0f);
}

// ---------------- launch ----------------
extern "C" void kernel_launch(void* const* d_in, const int* in_sizes, int n_in,
                              void* d_out, int out_size)
{
    const float* x    = (const float*)d_in[0];
    const float* W1   = (const float*)d_in[1];
    const float* b1   = (const float*)d_in[2];
    const float* W2   = (const float*)d_in[3];
    const float* b2   = (const float*)d_in[4];
    const float* W3   = (const float*)d_in[5];
    const float* b3   = (const float*)d_in[6];
    const void*  ei   = d_in[7];
    const void*  bidx = d_in[8];
    float* out = (float*)d_out;

    __half *x16, *tmp, *wh, *wl;
    cudaGetSymbolAddress((void**)&x16, g_x16);
    cudaGetSymbolAddress((void**)&tmp, g_tmp);
    cudaGetSymbolAddress((void**)&wh,  g_wh);
    cudaGetSymbolAddress((void**)&wl,  g_wl);
    (void)in_sizes; (void)n_in; (void)out_size;

    const int T = 256;
    int gemm_blocks = (NN + 127) / 128;
    int agg_blocks  = (NN * 32 + T - 1) / T;
    int cvt_blocks  = (NN * HH / 4 + T - 1) / T;   // covers convert + deg ranges

    init_kernel<<<(NN + T - 1) / T, T>>>(out, (const int*)ei);           // 0
    cvt_deg_kernel<<<cvt_blocks, T>>>(x, W1, W2, W3, ei);                // 1
    scan1_kernel<<<NP, SCAN_B>>>();                                      // 2
    scan2_kernel<<<1, 128>>>();                                          // 3
    fill_kernel<<<(EE + T - 1) / T, T>>>(ei);                            // 4
    gemm_f16_kernel<<<gemm_blocks, 256>>>(x16, wh, wl, tmp, NN);         // 5 (profiled)
    agg_kernel<<<agg_blocks, T>>>(tmp, b1, x16, 0, bidx, out);           // 6

    gemm_f16_kernel<<<gemm_blocks, 256>>>(x16, wh + HH*HH, wl + HH*HH, tmp, NN);
    agg_kernel<<<agg_blocks, T>>>(tmp, b2, x16, 0, bidx, out);

    gemm_f16_kernel<<<gemm_blocks, 256>>>(x16, wh + 2*HH*HH, wl + 2*HH*HH, tmp, NN);
    agg_kernel<<<agg_blocks, T>>>(tmp, b3, x16, 1, bidx, out);

    divide_kernel<<<(GG * HH + T - 1) / T, T>>>(out);
}